// round 3
// baseline (speedup 1.0000x reference)
#include <cuda_runtime.h>
#include <cuda_bf16.h>
#include <cstdint>

#define N_NODES 50000
#define N_EDGES 800000
#define RELS 8
#define BASES 30
#define DIM 128
#define NR (RELS * DIM)   // 1024

// ---------------- scratch (device globals; no allocation allowed) ----------------
__device__ float g_W[DIM * NR];                         // W2[k][r*128+o], 512KB
__device__ float g_xproj[(size_t)N_NODES * NR];         // [N,8,128] ~ 204.8MB
__device__ float g_h[(size_t)N_NODES * DIM];            // layer-1 output
__device__ float g_agg2[(size_t)N_NODES * DIM];         // layer-2 aggregate
__device__ int   g_deg[N_NODES + 1];
__device__ int   g_off[N_NODES + 1];
__device__ int   g_cur[N_NODES];
__device__ int   g_eidx[N_EDGES];

// ---------------- tiny kernels ----------------
__global__ void k_zero_deg() {
    int i = blockIdx.x * blockDim.x + threadIdx.x;
    if (i <= N_NODES) g_deg[i] = 0;
}

__global__ void k_hist(const int* __restrict__ ei) {
    int e = blockIdx.x * blockDim.x + threadIdx.x;
    if (e < N_EDGES) {
        int dst = ei[N_EDGES + e];
        if ((unsigned)dst < N_NODES) atomicAdd(&g_deg[dst], 1);
    }
}

// single-block exclusive scan over g_deg -> g_off (and copy to g_cur)
__global__ void k_scan() {
    __shared__ int s[1024];
    __shared__ int carry_s;
    if (threadIdx.x == 0) carry_s = 0;
    __syncthreads();
    for (int base = 0; base < N_NODES; base += 1024) {
        int i = base + threadIdx.x;
        int v = (i < N_NODES) ? g_deg[i] : 0;
        s[threadIdx.x] = v;
        __syncthreads();
        #pragma unroll
        for (int off = 1; off < 1024; off <<= 1) {
            int t = (threadIdx.x >= off) ? s[threadIdx.x - off] : 0;
            __syncthreads();
            s[threadIdx.x] += t;
            __syncthreads();
        }
        int excl = carry_s + s[threadIdx.x] - v;
        if (i < N_NODES) { g_off[i] = excl; g_cur[i] = excl; }
        int total = s[1023];
        __syncthreads();
        if (threadIdx.x == 0) carry_s += total;
        __syncthreads();
    }
    if (threadIdx.x == 0) g_off[N_NODES] = carry_s;
}

__global__ void k_scatter(const int* __restrict__ ei) {
    int e = blockIdx.x * blockDim.x + threadIdx.x;
    if (e < N_EDGES) {
        int dst = ei[N_EDGES + e];
        if ((unsigned)dst < N_NODES) {
            int p = atomicAdd(&g_cur[dst], 1);
            if ((unsigned)p < N_EDGES) g_eidx[p] = e;
        }
    }
}

// W2[k][r*128+o] = sum_b comp[r,b] * basis[b,k,o]
__global__ void k_W(const float* __restrict__ basis, const float* __restrict__ comp) {
    int idx = blockIdx.x * blockDim.x + threadIdx.x;   // over 8*128*128
    if (idx >= RELS * DIM * DIM) return;
    int o = idx & (DIM - 1);
    int k = (idx >> 7) & (DIM - 1);
    int r = idx >> 14;
    float s = 0.f;
    #pragma unroll
    for (int b = 0; b < BASES; b++)
        s += comp[r * BASES + b] * basis[((size_t)b * DIM + k) * DIM + o];
    g_W[k * NR + r * DIM + o] = s;
}

// ---------------- fp32 tiled GEMM: C[M,N] (+)= A[M,K] @ B[K,N] (+bias) ----------------
// Device-global operands are selected IN DEVICE CODE (no cudaGetSymbolAddress
// on the host — that tripped the harness in R1).
// AMODE: 0=param, 1=g_agg2, 2=g_h ; BMODE: 0=param, 1=g_W
// CMODE: 0=param, 1=g_xproj, 2=g_h
template<int AMODE, int BMODE, int CMODE, bool ADD_C, bool HAS_BIAS>
__global__ __launch_bounds__(256, 2)
void k_gemm(const float* __restrict__ Ap, const float* __restrict__ Bp,
            float* __restrict__ Cp, int M, int N, int K,
            const float* __restrict__ bias)
{
    const float* A = (AMODE == 0) ? Ap : (AMODE == 1 ? (const float*)g_agg2 : (const float*)g_h);
    const float* B = (BMODE == 0) ? Bp : (const float*)g_W;
    float*       C = (CMODE == 0) ? Cp : (CMODE == 1 ? g_xproj : g_h);

    __shared__ float As[16][132];
    __shared__ float Bs[16][128];
    int tid  = threadIdx.x;
    int trow = tid >> 4;        // 0..15
    int tcol = tid & 15;        // 0..15
    int m0 = blockIdx.y * 128;
    int n0 = blockIdx.x * 128;

    float acc[8][8];
    #pragma unroll
    for (int i = 0; i < 8; i++)
        #pragma unroll
        for (int j = 0; j < 8; j++) acc[i][j] = 0.f;

    for (int k0 = 0; k0 < K; k0 += 16) {
        // A tile: 128x16 = 512 float4
        #pragma unroll
        for (int l = 0; l < 2; l++) {
            int v = tid + l * 256;
            int row = v >> 2;
            int c4 = (v & 3) * 4;
            int m = m0 + row;
            float4 a = make_float4(0.f, 0.f, 0.f, 0.f);
            if (m < M) a = *(const float4*)&A[(size_t)m * K + k0 + c4];
            As[c4 + 0][row] = a.x;
            As[c4 + 1][row] = a.y;
            As[c4 + 2][row] = a.z;
            As[c4 + 3][row] = a.w;
        }
        // B tile: 16x128 = 512 float4
        #pragma unroll
        for (int l = 0; l < 2; l++) {
            int v = tid + l * 256;
            int row = v >> 5;
            int c = (v & 31) * 4;
            *(float4*)&Bs[row][c] = *(const float4*)&B[(size_t)(k0 + row) * N + n0 + c];
        }
        __syncthreads();
        #pragma unroll
        for (int k = 0; k < 16; k++) {
            float a[8], b[8];
            *(float4*)&a[0] = *(const float4*)&As[k][trow * 8];
            *(float4*)&a[4] = *(const float4*)&As[k][trow * 8 + 4];
            *(float4*)&b[0] = *(const float4*)&Bs[k][tcol * 8];
            *(float4*)&b[4] = *(const float4*)&Bs[k][tcol * 8 + 4];
            #pragma unroll
            for (int i = 0; i < 8; i++)
                #pragma unroll
                for (int j = 0; j < 8; j++)
                    acc[i][j] += a[i] * b[j];
        }
        __syncthreads();
    }

    #pragma unroll
    for (int i = 0; i < 8; i++) {
        int m = m0 + trow * 8 + i;
        if (m >= M) continue;
        #pragma unroll
        for (int j = 0; j < 8; j += 4) {
            int n = n0 + tcol * 8 + j;
            float4 r = make_float4(acc[i][j], acc[i][j + 1], acc[i][j + 2], acc[i][j + 3]);
            if (HAS_BIAS) {
                r.x += bias[n + 0]; r.y += bias[n + 1];
                r.z += bias[n + 2]; r.w += bias[n + 3];
            }
            if (ADD_C) {
                float4 c = *(const float4*)&C[(size_t)m * N + n];
                r.x += c.x; r.y += c.y; r.z += c.z; r.w += c.w;
            }
            *(float4*)&C[(size_t)m * N + n] = r;
        }
    }
}

// ---------------- pull aggregation: warp per node ----------------
// layer 1: g_h[n] = sum_{e: dst=n} norm[e] * x_proj[src[e], type[e], :]
__global__ void k_agg1(const int* __restrict__ ei, const int* __restrict__ et,
                       const float* __restrict__ norm)
{
    int n = blockIdx.x * (blockDim.x >> 5) + (threadIdx.x >> 5);
    if (n >= N_NODES) return;
    int lane = threadIdx.x & 31;
    int beg = g_off[n], end = g_off[n + 1];
    float4 acc = make_float4(0.f, 0.f, 0.f, 0.f);
    for (int p = beg; p < end; p++) {
        int e = g_eidx[p];
        int src = ei[e];
        int r = et[e];
        if ((unsigned)src >= N_NODES || (unsigned)r >= RELS) continue;
        float w = norm[e];
        float4 v = *((const float4*)(g_xproj + ((size_t)src * RELS + r) * DIM) + lane);
        acc.x += w * v.x; acc.y += w * v.y; acc.z += w * v.z; acc.w += w * v.w;
    }
    *((float4*)(g_h + (size_t)n * DIM) + lane) = acc;
}

// layer 2: g_agg2[n] = sum_{e: dst=n} g_h[src[e], :]
__global__ void k_agg2(const int* __restrict__ ei)
{
    int n = blockIdx.x * (blockDim.x >> 5) + (threadIdx.x >> 5);
    if (n >= N_NODES) return;
    int lane = threadIdx.x & 31;
    int beg = g_off[n], end = g_off[n + 1];
    float4 acc = make_float4(0.f, 0.f, 0.f, 0.f);
    for (int p = beg; p < end; p++) {
        int e = g_eidx[p];
        int src = ei[e];
        if ((unsigned)src >= N_NODES) continue;
        float4 v = *((const float4*)(g_h + (size_t)src * DIM) + lane);
        acc.x += v.x; acc.y += v.y; acc.z += v.z; acc.w += v.w;
    }
    *((float4*)(g_agg2 + (size_t)n * DIM) + lane) = acc;
}

// ---------------- launch ----------------
extern "C" void kernel_launch(void* const* d_in, const int* in_sizes, int n_in,
                              void* d_out, int out_size)
{
    const float* x      = (const float*)d_in[0];
    const int*   ei     = (const int*)d_in[1];    // int64 in reference -> delivered as int32
    const int*   et     = (const int*)d_in[2];    // int64 in reference -> delivered as int32
    const float* norm   = (const float*)d_in[3];
    const float* basis  = (const float*)d_in[4];
    const float* comp   = (const float*)d_in[5];
    const float* root   = (const float*)d_in[6];
    const float* bias1  = (const float*)d_in[7];
    const float* w_rel  = (const float*)d_in[8];
    const float* b_rel  = (const float*)d_in[9];
    const float* w_root = (const float*)d_in[10];
    float* out = (float*)d_out;

    // ---- CSR build (by dst) ----
    k_zero_deg<<<(N_NODES + 256) / 256, 256>>>();
    k_hist<<<(N_EDGES + 255) / 256, 256>>>(ei);
    k_scan<<<1, 1024>>>();
    k_scatter<<<(N_EDGES + 255) / 256, 256>>>(ei);

    // ---- relation weights ----
    k_W<<<(RELS * DIM * DIM + 255) / 256, 256>>>(basis, comp);

    // ---- layer 1 ----
    {   // x_proj = x @ W2   [50000,128] x [128,1024]
        dim3 grid(NR / 128, (N_NODES + 127) / 128);
        k_gemm<0, 1, 1, false, false><<<grid, 256>>>(x, nullptr, nullptr, N_NODES, NR, DIM, nullptr);
    }
    k_agg1<<<(N_NODES + 7) / 8, 256>>>(ei, et, norm);
    {   // h = agg + x @ root + bias1   (g_h already holds agg)
        dim3 grid(1, (N_NODES + 127) / 128);
        k_gemm<0, 0, 2, true, true><<<grid, 256>>>(x, root, nullptr, N_NODES, DIM, DIM, bias1);
    }

    // ---- layer 2 ----
    k_agg2<<<(N_NODES + 7) / 8, 256>>>(ei);
    {   // out = agg2 @ w_rel + b_rel
        dim3 grid(1, (N_NODES + 127) / 128);
        k_gemm<1, 0, 0, false, true><<<grid, 256>>>(nullptr, w_rel, out, N_NODES, DIM, DIM, b_rel);
    }
    {   // out += h @ w_root
        dim3 grid(1, (N_NODES + 127) / 128);
        k_gemm<2, 0, 0, true, false><<<grid, 256>>>(nullptr, w_root, out, N_NODES, DIM, DIM, nullptr);
    }
}

// round 4
// speedup vs baseline: 1.6375x; 1.6375x over previous
#include <cuda_runtime.h>
#include <cuda_bf16.h>
#include <cstdint>

#define N_NODES 50000
#define N_EDGES 800000
#define RELS 8
#define BASES 30
#define DIM 128
#define NR (RELS * DIM)   // 1024

// ---------------- scratch (device globals; no allocation allowed) ----------------
__device__ float g_W[DIM * NR];                         // W2[k][r*128+o], 512KB
__device__ float g_xproj[(size_t)N_NODES * NR];         // [N,8,128] ~ 204.8MB
__device__ float g_h[(size_t)N_NODES * DIM];            // layer-1 output
__device__ float g_agg2[(size_t)N_NODES * DIM];         // layer-2 aggregate
__device__ int   g_deg[N_NODES + 1];
__device__ int   g_off[N_NODES + 1];
__device__ int   g_cur[N_NODES];
__device__ int   g_eidx[N_EDGES];

// ---------------- tiny kernels ----------------
__global__ void k_zero_deg() {
    int i = blockIdx.x * blockDim.x + threadIdx.x;
    if (i <= N_NODES) g_deg[i] = 0;
}

__global__ void k_hist(const int* __restrict__ ei) {
    int e = blockIdx.x * blockDim.x + threadIdx.x;
    if (e < N_EDGES) {
        int dst = ei[N_EDGES + e];
        if ((unsigned)dst < N_NODES) atomicAdd(&g_deg[dst], 1);
    }
}

// single-block exclusive scan over g_deg -> g_off (warp-shuffle based)
__global__ void k_scan() {
    __shared__ int s[32];           // per-warp totals
    int tid = threadIdx.x;
    int lane = tid & 31;
    int wid = tid >> 5;
    int carry = 0;                  // every thread tracks the running total
    for (int base = 0; base < N_NODES; base += 1024) {
        int i = base + tid;
        int v = (i < N_NODES) ? g_deg[i] : 0;
        // inclusive warp scan
        int x = v;
        #pragma unroll
        for (int off = 1; off < 32; off <<= 1) {
            int t = __shfl_up_sync(0xffffffffu, x, off);
            if (lane >= off) x += t;
        }
        if (lane == 31) s[wid] = x;
        __syncthreads();
        if (wid == 0) {
            int w = s[lane];
            #pragma unroll
            for (int off = 1; off < 32; off <<= 1) {
                int t = __shfl_up_sync(0xffffffffu, w, off);
                if (lane >= off) w += t;
            }
            s[lane] = w;
        }
        __syncthreads();
        int warp_off = (wid > 0) ? s[wid - 1] : 0;
        int excl = carry + warp_off + x - v;
        if (i < N_NODES) { g_off[i] = excl; g_cur[i] = excl; }
        int total = s[31];
        __syncthreads();            // protect s[] before next chunk overwrites
        carry += total;
    }
    if (tid == 0) g_off[N_NODES] = carry;
}

__global__ void k_scatter(const int* __restrict__ ei) {
    int e = blockIdx.x * blockDim.x + threadIdx.x;
    if (e < N_EDGES) {
        int dst = ei[N_EDGES + e];
        if ((unsigned)dst < N_NODES) {
            int p = atomicAdd(&g_cur[dst], 1);
            if ((unsigned)p < N_EDGES) g_eidx[p] = e;
        }
    }
}

// W2[k][r*128+o] = sum_b comp[r,b] * basis[b,k,o]
__global__ void k_W(const float* __restrict__ basis, const float* __restrict__ comp) {
    int idx = blockIdx.x * blockDim.x + threadIdx.x;   // over 8*128*128
    if (idx >= RELS * DIM * DIM) return;
    int o = idx & (DIM - 1);
    int k = (idx >> 7) & (DIM - 1);
    int r = idx >> 14;
    float s = 0.f;
    #pragma unroll
    for (int b = 0; b < BASES; b++)
        s += comp[r * BASES + b] * basis[((size_t)b * DIM + k) * DIM + o];
    g_W[k * NR + r * DIM + o] = s;
}

// ---------------- tf32 tensor-core GEMM ----------------
// C[M,N] (+)= A[M,K] @ B[K,N] (+bias), fp32 accumulate, tf32 (rna) inputs.
// Block = 128x128 tile, 256 threads = 8 warps (2m x 4n), warp tile 64x32,
// warp does 4x4 of mma.m16n8k8.
// Device-global operands selected IN DEVICE CODE (no cudaGetSymbolAddress).
// AMODE: 0=param, 1=g_agg2, 2=g_h ; BMODE: 0=param, 1=g_W
// CMODE: 0=param, 1=g_xproj, 2=g_h

__device__ __forceinline__ uint32_t f2tf(float f) {
    uint32_t u;
    asm volatile("cvt.rna.tf32.f32 %0, %1;" : "=r"(u) : "f"(f));
    return u;
}

__device__ __forceinline__ void mma_tf32(float* c, const uint32_t* a, const uint32_t* b) {
    asm volatile(
        "mma.sync.aligned.m16n8k8.row.col.f32.tf32.tf32.f32 "
        "{%0,%1,%2,%3}, {%4,%5,%6,%7}, {%8,%9}, {%0,%1,%2,%3};"
        : "+f"(c[0]), "+f"(c[1]), "+f"(c[2]), "+f"(c[3])
        : "r"(a[0]), "r"(a[1]), "r"(a[2]), "r"(a[3]), "r"(b[0]), "r"(b[1]));
}

template<int AMODE, int BMODE, int CMODE, bool ADD_C, bool HAS_BIAS>
__global__ __launch_bounds__(256, 2)
void k_gemm_tc(const float* __restrict__ Ap, const float* __restrict__ Bp,
               float* __restrict__ Cp, int M, int N, int K,
               const float* __restrict__ bias)
{
    const float* A = (AMODE == 0) ? Ap : (AMODE == 1 ? (const float*)g_agg2 : (const float*)g_h);
    const float* B = (BMODE == 0) ? Bp : (const float*)g_W;
    float*       C = (CMODE == 0) ? Cp : (CMODE == 1 ? g_xproj : g_h);

    __shared__ uint32_t As[16][132];   // As[k][m], tf32 bits, pad->conflict-free
    __shared__ uint32_t Bs[16][132];   // Bs[k][n]

    int tid  = threadIdx.x;
    int lane = tid & 31;
    int wid  = tid >> 5;
    int warp_m = wid & 1;              // 0..1
    int warp_n = wid >> 1;             // 0..3
    int m0 = blockIdx.y * 128;
    int n0 = blockIdx.x * 128;
    int r  = lane >> 2;                // 0..7
    int cq = lane & 3;                 // 0..3

    float acc[4][4][4];
    #pragma unroll
    for (int mt = 0; mt < 4; mt++)
        #pragma unroll
        for (int nt = 0; nt < 4; nt++)
            #pragma unroll
            for (int i = 0; i < 4; i++) acc[mt][nt][i] = 0.f;

    for (int k0 = 0; k0 < K; k0 += 16) {
        // A tile: 128 rows x 16 cols -> As[k][m]
        #pragma unroll
        for (int l = 0; l < 2; l++) {
            int v = tid + l * 256;
            int row = v >> 2;
            int c4 = (v & 3) * 4;
            int m = m0 + row;
            float4 a = make_float4(0.f, 0.f, 0.f, 0.f);
            if (m < M) a = *(const float4*)&A[(size_t)m * K + k0 + c4];
            As[c4 + 0][row] = f2tf(a.x);
            As[c4 + 1][row] = f2tf(a.y);
            As[c4 + 2][row] = f2tf(a.z);
            As[c4 + 3][row] = f2tf(a.w);
        }
        // B tile: 16 rows x 128 cols -> Bs[k][n]
        #pragma unroll
        for (int l = 0; l < 2; l++) {
            int v = tid + l * 256;
            int row = v >> 5;
            int c = (v & 31) * 4;
            float4 b = *(const float4*)&B[(size_t)(k0 + row) * N + n0 + c];
            Bs[row][c + 0] = f2tf(b.x);
            Bs[row][c + 1] = f2tf(b.y);
            Bs[row][c + 2] = f2tf(b.z);
            Bs[row][c + 3] = f2tf(b.w);
        }
        __syncthreads();

        #pragma unroll
        for (int kk = 0; kk < 16; kk += 8) {
            uint32_t afr[4][4], bfr[4][2];
            #pragma unroll
            for (int mt = 0; mt < 4; mt++) {
                int mb = warp_m * 64 + mt * 16;
                afr[mt][0] = As[kk + cq][mb + r];
                afr[mt][1] = As[kk + cq][mb + r + 8];
                afr[mt][2] = As[kk + cq + 4][mb + r];
                afr[mt][3] = As[kk + cq + 4][mb + r + 8];
            }
            #pragma unroll
            for (int nt = 0; nt < 4; nt++) {
                int nb = warp_n * 32 + nt * 8;
                bfr[nt][0] = Bs[kk + cq][nb + r];
                bfr[nt][1] = Bs[kk + cq + 4][nb + r];
            }
            #pragma unroll
            for (int mt = 0; mt < 4; mt++)
                #pragma unroll
                for (int nt = 0; nt < 4; nt++)
                    mma_tf32(acc[mt][nt], afr[mt], bfr[nt]);
        }
        __syncthreads();
    }

    // epilogue: c0,c1 -> (row, 2cq..2cq+1); c2,c3 -> (row+8, ...)
    #pragma unroll
    for (int mt = 0; mt < 4; mt++) {
        int mA = m0 + warp_m * 64 + mt * 16 + r;
        #pragma unroll
        for (int nt = 0; nt < 4; nt++) {
            int n = n0 + warp_n * 32 + nt * 8 + 2 * cq;
            if (mA < M) {
                float2 v = make_float2(acc[mt][nt][0], acc[mt][nt][1]);
                if (HAS_BIAS) { v.x += bias[n]; v.y += bias[n + 1]; }
                if (ADD_C) {
                    float2 o = *(const float2*)&C[(size_t)mA * N + n];
                    v.x += o.x; v.y += o.y;
                }
                *(float2*)&C[(size_t)mA * N + n] = v;
            }
            int mB = mA + 8;
            if (mB < M) {
                float2 v = make_float2(acc[mt][nt][2], acc[mt][nt][3]);
                if (HAS_BIAS) { v.x += bias[n]; v.y += bias[n + 1]; }
                if (ADD_C) {
                    float2 o = *(const float2*)&C[(size_t)mB * N + n];
                    v.x += o.x; v.y += o.y;
                }
                *(float2*)&C[(size_t)mB * N + n] = v;
            }
        }
    }
}

// ---------------- pull aggregation: warp per node ----------------
// layer 1: g_h[n] = sum_{e: dst=n} norm[e] * x_proj[src[e], type[e], :]
__global__ void k_agg1(const int* __restrict__ ei, const int* __restrict__ et,
                       const float* __restrict__ norm)
{
    int n = blockIdx.x * (blockDim.x >> 5) + (threadIdx.x >> 5);
    if (n >= N_NODES) return;
    int lane = threadIdx.x & 31;
    int beg = g_off[n], end = g_off[n + 1];
    float4 acc = make_float4(0.f, 0.f, 0.f, 0.f);
    for (int p = beg; p < end; p++) {
        int e = g_eidx[p];
        int src = ei[e];
        int r = et[e];
        if ((unsigned)src >= N_NODES || (unsigned)r >= RELS) continue;
        float w = norm[e];
        float4 v = *((const float4*)(g_xproj + ((size_t)src * RELS + r) * DIM) + lane);
        acc.x += w * v.x; acc.y += w * v.y; acc.z += w * v.z; acc.w += w * v.w;
    }
    *((float4*)(g_h + (size_t)n * DIM) + lane) = acc;
}

// layer 2: g_agg2[n] = sum_{e: dst=n} g_h[src[e], :]
__global__ void k_agg2(const int* __restrict__ ei)
{
    int n = blockIdx.x * (blockDim.x >> 5) + (threadIdx.x >> 5);
    if (n >= N_NODES) return;
    int lane = threadIdx.x & 31;
    int beg = g_off[n], end = g_off[n + 1];
    float4 acc = make_float4(0.f, 0.f, 0.f, 0.f);
    for (int p = beg; p < end; p++) {
        int e = g_eidx[p];
        int src = ei[e];
        if ((unsigned)src >= N_NODES) continue;
        float4 v = *((const float4*)(g_h + (size_t)src * DIM) + lane);
        acc.x += v.x; acc.y += v.y; acc.z += v.z; acc.w += v.w;
    }
    *((float4*)(g_agg2 + (size_t)n * DIM) + lane) = acc;
}

// ---------------- launch ----------------
extern "C" void kernel_launch(void* const* d_in, const int* in_sizes, int n_in,
                              void* d_out, int out_size)
{
    const float* x      = (const float*)d_in[0];
    const int*   ei     = (const int*)d_in[1];    // int64 in reference -> delivered as int32
    const int*   et     = (const int*)d_in[2];
    const float* norm   = (const float*)d_in[3];
    const float* basis  = (const float*)d_in[4];
    const float* comp   = (const float*)d_in[5];
    const float* root   = (const float*)d_in[6];
    const float* bias1  = (const float*)d_in[7];
    const float* w_rel  = (const float*)d_in[8];
    const float* b_rel  = (const float*)d_in[9];
    const float* w_root = (const float*)d_in[10];
    float* out = (float*)d_out;

    // ---- CSR build (by dst) ----
    k_zero_deg<<<(N_NODES + 256) / 256, 256>>>();
    k_hist<<<(N_EDGES + 255) / 256, 256>>>(ei);
    k_scan<<<1, 1024>>>();
    k_scatter<<<(N_EDGES + 255) / 256, 256>>>(ei);

    // ---- relation weights ----
    k_W<<<(RELS * DIM * DIM + 255) / 256, 256>>>(basis, comp);

    // ---- layer 1 ----
    {   // x_proj = x @ W2   [50000,128] x [128,1024]
        dim3 grid(NR / 128, (N_NODES + 127) / 128);
        k_gemm_tc<0, 1, 1, false, false><<<grid, 256>>>(x, nullptr, nullptr, N_NODES, NR, DIM, nullptr);
    }
    k_agg1<<<(N_NODES + 7) / 8, 256>>>(ei, et, norm);
    {   // h = agg + x @ root + bias1   (g_h already holds agg)
        dim3 grid(1, (N_NODES + 127) / 128);
        k_gemm_tc<0, 0, 2, true, true><<<grid, 256>>>(x, root, nullptr, N_NODES, DIM, DIM, bias1);
    }

    // ---- layer 2 ----
    k_agg2<<<(N_NODES + 7) / 8, 256>>>(ei);
    {   // out = agg2 @ w_rel + b_rel
        dim3 grid(1, (N_NODES + 127) / 128);
        k_gemm_tc<1, 0, 0, false, true><<<grid, 256>>>(nullptr, w_rel, out, N_NODES, DIM, DIM, b_rel);
    }
    {   // out += h @ w_root
        dim3 grid(1, (N_NODES + 127) / 128);
        k_gemm_tc<2, 0, 0, true, false><<<grid, 256>>>(nullptr, w_root, out, N_NODES, DIM, DIM, nullptr);
    }
}

// round 5
// speedup vs baseline: 1.9537x; 1.1931x over previous
#include <cuda_runtime.h>
#include <cuda_bf16.h>
#include <cstdint>

#define N_NODES 50000
#define N_EDGES 800000
#define RELS 8
#define BASES 30
#define DIM 128
#define NR (RELS * DIM)   // 1024

// ---------------- scratch (device globals; no allocation allowed) ----------------
__device__ float g_W[DIM * NR];                         // W2[k][r*128+o], 512KB
__device__ float g_xproj[(size_t)N_NODES * NR];         // [N,8,128] ~ 204.8MB
__device__ float g_h[(size_t)N_NODES * DIM];            // layer-1 output
__device__ float g_agg2[(size_t)N_NODES * DIM];         // layer-2 aggregate
__device__ int   g_deg[N_NODES + 1];
__device__ int   g_off[N_NODES + 1];
__device__ int   g_cur[N_NODES];
__device__ int   g_pack[N_EDGES];                       // CSR-ordered src | rel<<17
__device__ float g_pw[N_EDGES];                         // CSR-ordered edge_norm

// ---------------- tiny kernels ----------------
__global__ void k_zero_deg() {
    int i = blockIdx.x * blockDim.x + threadIdx.x;
    if (i <= N_NODES) g_deg[i] = 0;
}

__global__ void k_hist(const int* __restrict__ ei) {
    int e = blockIdx.x * blockDim.x + threadIdx.x;
    if (e < N_EDGES) {
        int dst = ei[N_EDGES + e];
        if ((unsigned)dst < N_NODES) atomicAdd(&g_deg[dst], 1);
    }
}

// single-block exclusive scan over g_deg -> g_off (warp-shuffle based)
__global__ void k_scan() {
    __shared__ int s[32];
    int tid = threadIdx.x;
    int lane = tid & 31;
    int wid = tid >> 5;
    int carry = 0;
    for (int base = 0; base < N_NODES; base += 1024) {
        int i = base + tid;
        int v = (i < N_NODES) ? g_deg[i] : 0;
        int x = v;
        #pragma unroll
        for (int off = 1; off < 32; off <<= 1) {
            int t = __shfl_up_sync(0xffffffffu, x, off);
            if (lane >= off) x += t;
        }
        if (lane == 31) s[wid] = x;
        __syncthreads();
        if (wid == 0) {
            int w = s[lane];
            #pragma unroll
            for (int off = 1; off < 32; off <<= 1) {
                int t = __shfl_up_sync(0xffffffffu, w, off);
                if (lane >= off) w += t;
            }
            s[lane] = w;
        }
        __syncthreads();
        int warp_off = (wid > 0) ? s[wid - 1] : 0;
        int excl = carry + warp_off + x - v;
        if (i < N_NODES) { g_off[i] = excl; g_cur[i] = excl; }
        int total = s[31];
        __syncthreads();
        carry += total;
    }
    if (tid == 0) g_off[N_NODES] = carry;
}

// scatter edges into CSR order, packing {src, rel} and norm for coalesced agg reads
__global__ void k_scatter(const int* __restrict__ ei, const int* __restrict__ et,
                          const float* __restrict__ norm) {
    int e = blockIdx.x * blockDim.x + threadIdx.x;
    if (e < N_EDGES) {
        int dst = ei[N_EDGES + e];
        if ((unsigned)dst < N_NODES) {
            int src = ei[e];
            int rel = et[e];
            int p = atomicAdd(&g_cur[dst], 1);
            bool ok = (unsigned)src < N_NODES && (unsigned)rel < RELS;
            g_pack[p] = ok ? (src | (rel << 17)) : 0;
            g_pw[p]   = ok ? norm[e] : 0.f;
        }
    }
}

// W2[k][r*128+o] = sum_b comp[r,b] * basis[b,k,o]
__global__ void k_W(const float* __restrict__ basis, const float* __restrict__ comp) {
    int idx = blockIdx.x * blockDim.x + threadIdx.x;
    if (idx >= RELS * DIM * DIM) return;
    int o = idx & (DIM - 1);
    int k = (idx >> 7) & (DIM - 1);
    int r = idx >> 14;
    float s = 0.f;
    #pragma unroll
    for (int b = 0; b < BASES; b++)
        s += comp[r * BASES + b] * basis[((size_t)b * DIM + k) * DIM + o];
    g_W[k * NR + r * DIM + o] = s;
}

// ---------------- tf32 tensor-core GEMM (double-buffered, conflict-free smem) ----
// C[M,N] (+)= A[M,K] @ B[K,N] (+bias), fp32 accumulate, tf32(rna) inputs.
// 128x128 block tile, 256 threads = 8 warps (2m x 4n), warp 64x32, 4x4 m16n8k8.
// AMODE: 0=param, 3=concat[g_agg2|g_h] (KT=256)
// BMODE: 0=param(Bp), 1=g_W, 2=concat[Bp|Bp2] (KT=256)
// CMODE: 0=param, 1=g_xproj, 2=g_h

__device__ __forceinline__ uint32_t f2tf(float f) {
    uint32_t u;
    asm volatile("cvt.rna.tf32.f32 %0, %1;" : "=r"(u) : "f"(f));
    return u;
}

__device__ __forceinline__ void mma_tf32(float* c, const uint32_t* a, const uint32_t* b) {
    asm volatile(
        "mma.sync.aligned.m16n8k8.row.col.f32.tf32.tf32.f32 "
        "{%0,%1,%2,%3}, {%4,%5,%6,%7}, {%8,%9}, {%0,%1,%2,%3};"
        : "+f"(c[0]), "+f"(c[1]), "+f"(c[2]), "+f"(c[3])
        : "r"(a[0]), "r"(a[1]), "r"(a[2]), "r"(a[3]), "r"(b[0]), "r"(b[1]));
}

template<int KT, int AMODE, int BMODE, int CMODE, bool ADD_C, bool HAS_BIAS>
__global__ __launch_bounds__(256, 2)
void k_gemm_tc(const float* __restrict__ Ap, const float* __restrict__ Bp,
               const float* __restrict__ Bp2, float* __restrict__ Cp,
               int M, int N, const float* __restrict__ bias)
{
    __shared__ uint32_t As[2][128][20];   // m-major, pad 20 -> conflict-free frag reads
    __shared__ uint32_t Bs[2][16][136];   // k-major, pad 136 -> conflict-free frag reads

    int tid  = threadIdx.x;
    int lane = tid & 31;
    int wid  = tid >> 5;
    int warp_m = wid & 1;
    int warp_n = wid >> 1;
    int m0 = blockIdx.y * 128;
    int n0 = blockIdx.x * 128;
    int r  = lane >> 2;
    int cq = lane & 3;

    float acc[4][4][4];
    #pragma unroll
    for (int mt = 0; mt < 4; mt++)
        #pragma unroll
        for (int nt = 0; nt < 4; nt++)
            #pragma unroll
            for (int i = 0; i < 4; i++) acc[mt][nt][i] = 0.f;

    float4 aReg[2], bReg[2];

    auto LDG_chunk = [&](int k0) {
        const float* Asrc; int astride; int acol;
        if (AMODE == 3) {
            Asrc = (k0 < DIM) ? (const float*)g_agg2 : (const float*)g_h;
            acol = k0 & (DIM - 1); astride = DIM;
        } else { Asrc = Ap; acol = k0; astride = KT; }
        #pragma unroll
        for (int l = 0; l < 2; l++) {
            int idx = tid + l * 256;
            int m = idx >> 2;
            int c4 = (idx & 3) * 4;
            int gm = m0 + m;
            aReg[l] = (gm < M) ? *(const float4*)&Asrc[(size_t)gm * astride + acol + c4]
                               : make_float4(0.f, 0.f, 0.f, 0.f);
        }
        const float* Bsrc; int brow;
        if (BMODE == 2) { Bsrc = (k0 < DIM) ? Bp : Bp2; brow = k0 & (DIM - 1); }
        else if (BMODE == 1) { Bsrc = (const float*)g_W; brow = k0; }
        else { Bsrc = Bp; brow = k0; }
        #pragma unroll
        for (int l = 0; l < 2; l++) {
            int idx = tid + l * 256;
            int kr = idx >> 5;
            int c = (idx & 31) * 4;
            bReg[l] = *(const float4*)&Bsrc[(size_t)(brow + kr) * N + n0 + c];
        }
    };

    auto STS_chunk = [&](int buf) {
        #pragma unroll
        for (int l = 0; l < 2; l++) {
            int idx = tid + l * 256;
            int m = idx >> 2;
            int c4 = (idx & 3) * 4;
            *(uint4*)&As[buf][m][c4] =
                make_uint4(f2tf(aReg[l].x), f2tf(aReg[l].y), f2tf(aReg[l].z), f2tf(aReg[l].w));
        }
        #pragma unroll
        for (int l = 0; l < 2; l++) {
            int idx = tid + l * 256;
            int kr = idx >> 5;
            int c = (idx & 31) * 4;
            *(uint4*)&Bs[buf][kr][c] =
                make_uint4(f2tf(bReg[l].x), f2tf(bReg[l].y), f2tf(bReg[l].z), f2tf(bReg[l].w));
        }
    };

    LDG_chunk(0);
    STS_chunk(0);
    __syncthreads();

    const int NC = KT / 16;
    #pragma unroll 1
    for (int c = 0; c < NC; c++) {
        if (c + 1 < NC) LDG_chunk((c + 1) * 16);
        int buf = c & 1;
        #pragma unroll
        for (int kk = 0; kk < 16; kk += 8) {
            uint32_t afr[4][4], bfr[4][2];
            #pragma unroll
            for (int mt = 0; mt < 4; mt++) {
                int mb = warp_m * 64 + mt * 16;
                afr[mt][0] = As[buf][mb + r][kk + cq];
                afr[mt][1] = As[buf][mb + r + 8][kk + cq];
                afr[mt][2] = As[buf][mb + r][kk + cq + 4];
                afr[mt][3] = As[buf][mb + r + 8][kk + cq + 4];
            }
            #pragma unroll
            for (int nt = 0; nt < 4; nt++) {
                int nb = warp_n * 32 + nt * 8;
                bfr[nt][0] = Bs[buf][kk + cq][nb + r];
                bfr[nt][1] = Bs[buf][kk + cq + 4][nb + r];
            }
            #pragma unroll
            for (int mt = 0; mt < 4; mt++)
                #pragma unroll
                for (int nt = 0; nt < 4; nt++)
                    mma_tf32(acc[mt][nt], afr[mt], bfr[nt]);
        }
        if (c + 1 < NC) {
            STS_chunk((c + 1) & 1);
            __syncthreads();
        }
    }

    float* C = (CMODE == 0) ? Cp : (CMODE == 1 ? g_xproj : g_h);
    #pragma unroll
    for (int mt = 0; mt < 4; mt++) {
        int mA = m0 + warp_m * 64 + mt * 16 + r;
        #pragma unroll
        for (int nt = 0; nt < 4; nt++) {
            int n = n0 + warp_n * 32 + nt * 8 + 2 * cq;
            if (mA < M) {
                float2 v = make_float2(acc[mt][nt][0], acc[mt][nt][1]);
                if (HAS_BIAS) { v.x += bias[n]; v.y += bias[n + 1]; }
                if (ADD_C) {
                    float2 o = *(const float2*)&C[(size_t)mA * N + n];
                    v.x += o.x; v.y += o.y;
                }
                *(float2*)&C[(size_t)mA * N + n] = v;
            }
            int mB = mA + 8;
            if (mB < M) {
                float2 v = make_float2(acc[mt][nt][2], acc[mt][nt][3]);
                if (HAS_BIAS) { v.x += bias[n]; v.y += bias[n + 1]; }
                if (ADD_C) {
                    float2 o = *(const float2*)&C[(size_t)mB * N + n];
                    v.x += o.x; v.y += o.y;
                }
                *(float2*)&C[(size_t)mB * N + n] = v;
            }
        }
    }
}

// ---------------- pull aggregation: warp per node ----------------
// layer 1: g_h[n] = sum_{p in CSR[n]} w_p * x_proj[src_p, rel_p, :]
__global__ void k_agg1()
{
    int n = blockIdx.x * (blockDim.x >> 5) + (threadIdx.x >> 5);
    if (n >= N_NODES) return;
    int lane = threadIdx.x & 31;
    int beg = g_off[n], end = g_off[n + 1];
    float4 acc = make_float4(0.f, 0.f, 0.f, 0.f);
    for (int p = beg; p < end; p++) {
        int pk = g_pack[p];
        int src = pk & 0x1FFFF;
        int rl = pk >> 17;
        float w = g_pw[p];
        float4 v = *((const float4*)(g_xproj + ((size_t)src * RELS + rl) * DIM) + lane);
        acc.x += w * v.x; acc.y += w * v.y; acc.z += w * v.z; acc.w += w * v.w;
    }
    *((float4*)(g_h + (size_t)n * DIM) + lane) = acc;
}

// layer 2: g_agg2[n] = sum_{p in CSR[n]} g_h[src_p, :]
__global__ void k_agg2()
{
    int n = blockIdx.x * (blockDim.x >> 5) + (threadIdx.x >> 5);
    if (n >= N_NODES) return;
    int lane = threadIdx.x & 31;
    int beg = g_off[n], end = g_off[n + 1];
    float4 acc = make_float4(0.f, 0.f, 0.f, 0.f);
    for (int p = beg; p < end; p++) {
        int src = g_pack[p] & 0x1FFFF;
        float4 v = *((const float4*)(g_h + (size_t)src * DIM) + lane);
        acc.x += v.x; acc.y += v.y; acc.z += v.z; acc.w += v.w;
    }
    *((float4*)(g_agg2 + (size_t)n * DIM) + lane) = acc;
}

// ---------------- launch ----------------
extern "C" void kernel_launch(void* const* d_in, const int* in_sizes, int n_in,
                              void* d_out, int out_size)
{
    const float* x      = (const float*)d_in[0];
    const int*   ei     = (const int*)d_in[1];    // int64 in reference -> delivered as int32
    const int*   et     = (const int*)d_in[2];
    const float* norm   = (const float*)d_in[3];
    const float* basis  = (const float*)d_in[4];
    const float* comp   = (const float*)d_in[5];
    const float* root   = (const float*)d_in[6];
    const float* bias1  = (const float*)d_in[7];
    const float* w_rel  = (const float*)d_in[8];
    const float* b_rel  = (const float*)d_in[9];
    const float* w_root = (const float*)d_in[10];
    float* out = (float*)d_out;

    const int MBLK = (N_NODES + 127) / 128;

    // 1: relation weights (big GEMM depends only on this)
    k_W<<<(RELS * DIM * DIM + 255) / 256, 256>>>(basis, comp);
    // 2-3: CSR build front half
    k_zero_deg<<<(N_NODES + 256) / 256, 256>>>();
    k_hist<<<(N_EDGES + 255) / 256, 256>>>(ei);
    // 4: big GEMM  x_proj = x @ W2   [50000,128] x [128,1024]
    {
        dim3 grid(NR / 128, MBLK);
        k_gemm_tc<128, 0, 1, 1, false, false><<<grid, 256>>>(x, nullptr, nullptr, nullptr,
                                                             N_NODES, NR, nullptr);
    }
    // 5-6: CSR build back half
    k_scan<<<1, 1024>>>();
    k_scatter<<<(N_EDGES + 255) / 256, 256>>>(ei, et, norm);
    // 7: layer-1 aggregation -> g_h
    k_agg1<<<(N_NODES + 7) / 8, 256>>>();
    // 8: h = agg + x @ root + bias1  (accumulate onto g_h)
    {
        dim3 grid(1, MBLK);
        k_gemm_tc<128, 0, 0, 2, true, true><<<grid, 256>>>(x, root, nullptr, nullptr,
                                                           N_NODES, DIM, bias1);
    }
    // 9: layer-2 aggregation -> g_agg2
    k_agg2<<<(N_NODES + 7) / 8, 256>>>();
    // 10: out = [agg2, h] @ [w_rel; w_root] + b_rel   (fused K=256)
    {
        dim3 grid(1, MBLK);
        k_gemm_tc<256, 3, 2, 0, false, true><<<grid, 256>>>(nullptr, w_rel, w_root, out,
                                                            N_NODES, DIM, b_rel);
    }
}

// round 8
// speedup vs baseline: 2.2428x; 1.1480x over previous
#include <cuda_runtime.h>
#include <cuda_bf16.h>
#include <cstdint>
#include <type_traits>

#define N_NODES 50000
#define N_EDGES 800000
#define RELS 8
#define BASES 30
#define DIM 128
#define NR (RELS * DIM)   // 1024

// ---------------- scratch (device globals; no allocation allowed) ----------------
__device__ float g_W[DIM * NR];                         // W2[k][r*128+o], 512KB
__device__ float g_xproj[(size_t)N_NODES * NR];         // [N,8,128] ~ 204.8MB
__device__ float g_h[(size_t)N_NODES * DIM];            // layer-1 output
__device__ float g_agg2[(size_t)N_NODES * DIM];         // layer-2 aggregate
__device__ int   g_deg[N_NODES + 1];
__device__ int   g_off[N_NODES + 1];
__device__ int   g_cur[N_NODES];
__device__ int   g_pack[N_EDGES];                       // CSR-ordered src | rel<<17
__device__ float g_pw[N_EDGES];                         // CSR-ordered edge_norm

// ---------------- tiny kernels ----------------
__global__ void k_zero_deg() {
    int i = blockIdx.x * blockDim.x + threadIdx.x;
    if (i <= N_NODES) g_deg[i] = 0;
}

__global__ void k_hist(const int* __restrict__ ei) {
    int e = blockIdx.x * blockDim.x + threadIdx.x;
    if (e < N_EDGES) {
        int dst = ei[N_EDGES + e];
        if ((unsigned)dst < N_NODES) atomicAdd(&g_deg[dst], 1);
    }
}

// single-block exclusive scan over g_deg -> g_off (warp-shuffle based)
__global__ void k_scan() {
    __shared__ int s[32];
    int tid = threadIdx.x;
    int lane = tid & 31;
    int wid = tid >> 5;
    int carry = 0;
    for (int base = 0; base < N_NODES; base += 1024) {
        int i = base + tid;
        int v = (i < N_NODES) ? g_deg[i] : 0;
        int x = v;
        #pragma unroll
        for (int off = 1; off < 32; off <<= 1) {
            int t = __shfl_up_sync(0xffffffffu, x, off);
            if (lane >= off) x += t;
        }
        if (lane == 31) s[wid] = x;
        __syncthreads();
        if (wid == 0) {
            int w = s[lane];
            #pragma unroll
            for (int off = 1; off < 32; off <<= 1) {
                int t = __shfl_up_sync(0xffffffffu, w, off);
                if (lane >= off) w += t;
            }
            s[lane] = w;
        }
        __syncthreads();
        int warp_off = (wid > 0) ? s[wid - 1] : 0;
        int excl = carry + warp_off + x - v;
        if (i < N_NODES) { g_off[i] = excl; g_cur[i] = excl; }
        int total = s[31];
        __syncthreads();
        carry += total;
    }
    if (tid == 0) g_off[N_NODES] = carry;
}

// scatter edges into CSR order, packing {src, rel} and norm for coalesced agg reads
__global__ void k_scatter(const int* __restrict__ ei, const int* __restrict__ et,
                          const float* __restrict__ norm) {
    int e = blockIdx.x * blockDim.x + threadIdx.x;
    if (e < N_EDGES) {
        int dst = ei[N_EDGES + e];
        if ((unsigned)dst < N_NODES) {
            int src = ei[e];
            int rel = et[e];
            int p = atomicAdd(&g_cur[dst], 1);
            bool ok = (unsigned)src < N_NODES && (unsigned)rel < RELS;
            g_pack[p] = ok ? (src | (rel << 17)) : 0;
            g_pw[p]   = ok ? norm[e] : 0.f;
        }
    }
}

// W2[k][r*128+o] = sum_b comp[r,b] * basis[b,k,o]
__global__ void k_W(const float* __restrict__ basis, const float* __restrict__ comp) {
    int idx = blockIdx.x * blockDim.x + threadIdx.x;
    if (idx >= RELS * DIM * DIM) return;
    int o = idx & (DIM - 1);
    int k = (idx >> 7) & (DIM - 1);
    int r = idx >> 14;
    float s = 0.f;
    #pragma unroll
    for (int b = 0; b < BASES; b++)
        s += comp[r * BASES + b] * basis[((size_t)b * DIM + k) * DIM + o];
    g_W[k * NR + r * DIM + o] = s;
}

// ---------------- tf32 tensor-core GEMM ----------------
// C[M,N] (+)= A[M,K] @ B[K,N] (+bias), fp32 accumulate, tf32(rna) inputs.
// 128x128 block, 256 threads = 8 warps (2m x 4n), warp 64x32, 4x4 m16n8k8.
// A smem: m-major, k-interleaved pairs (slot(k) = (k&8)|2(k&3)|((k>>2)&1)),
// row stride 24 words -> LDS.64 fragment loads, conflict-free.
// B smem: k-major, stride 136 -> conflict-free 32-bit loads, STS.128 fills.
// NOTE: LDG_chunk's argument is an ELEMENT k-offset (multiple of 16), not a
// chunk index — R6/R7's misaligned-address fault was calling it with c+1.
// AMODE: 0=param, 3=concat[g_agg2|g_h] (KT=256)
// BMODE: 0=param(Bp), 1=g_W, 2=concat[Bp|Bp2] (KT=256)
// CMODE: 0=param, 1=g_xproj, 2=g_h

__device__ __forceinline__ uint32_t f2tf(float f) {
    uint32_t u;
    asm volatile("cvt.rna.tf32.f32 %0, %1;" : "=r"(u) : "f"(f));
    return u;
}

__device__ __forceinline__ void mma_tf32(float* c, const uint32_t* a, const uint32_t* b) {
    asm volatile(
        "mma.sync.aligned.m16n8k8.row.col.f32.tf32.tf32.f32 "
        "{%0,%1,%2,%3}, {%4,%5,%6,%7}, {%8,%9}, {%0,%1,%2,%3};"
        : "+f"(c[0]), "+f"(c[1]), "+f"(c[2]), "+f"(c[3])
        : "r"(a[0]), "r"(a[1]), "r"(a[2]), "r"(a[3]), "r"(b[0]), "r"(b[1]));
}

template<int KT, int AMODE, int BMODE, int CMODE, bool ADD_C, bool HAS_BIAS>
__global__ __launch_bounds__(256, 2)
void k_gemm_tc(const float* __restrict__ Ap, const float* __restrict__ Bp,
               const float* __restrict__ Bp2, float* __restrict__ Cp,
               int M, int N, const float* __restrict__ bias)
{
    __shared__ __align__(16) uint32_t As[2][128][24];
    __shared__ __align__(16) uint32_t Bs[2][16][136];

    int tid  = threadIdx.x;
    int lane = tid & 31;
    int wid  = tid >> 5;
    int warp_m = wid & 1;
    int warp_n = wid >> 1;
    int m0 = blockIdx.y * 128;
    int n0 = blockIdx.x * 128;
    int r  = lane >> 2;
    int cq = lane & 3;

    float acc[4][4][4];
    #pragma unroll
    for (int mt = 0; mt < 4; mt++)
        #pragma unroll
        for (int nt = 0; nt < 4; nt++)
            #pragma unroll
            for (int i = 0; i < 4; i++) acc[mt][nt][i] = 0.f;

    float4 aReg[2], bReg[2];

    // per-thread fill coords (constant over loop)
    const int fa_m  = tid >> 2;          // A: row within tile (0..63, +64 for l=1)
    const int fa_c4 = (tid & 3) * 4;     // A: k-quad base
    const int fa_s0 = (fa_c4 & 8) | ((fa_c4 >> 2) & 1);   // interleave slot base

    auto LDG_chunk = [&](int k0) {       // k0 = element offset in K, multiple of 16
        const float* Asrc; int astride; int acol;
        if (AMODE == 3) {
            Asrc = (k0 < DIM) ? (const float*)g_agg2 : (const float*)g_h;
            acol = k0 & (DIM - 1); astride = DIM;
        } else { Asrc = Ap; acol = k0; astride = KT; }
        #pragma unroll
        for (int l = 0; l < 2; l++) {
            int gm = m0 + fa_m + l * 64;
            aReg[l] = (gm < M) ? *(const float4*)&Asrc[(size_t)gm * astride + acol + fa_c4]
                               : make_float4(0.f, 0.f, 0.f, 0.f);
        }
        const float* Bsrc; int brow;
        if (BMODE == 2) { Bsrc = (k0 < DIM) ? Bp : Bp2; brow = k0 & (DIM - 1); }
        else if (BMODE == 1) { Bsrc = (const float*)g_W; brow = k0; }
        else { Bsrc = Bp; brow = k0; }
        #pragma unroll
        for (int l = 0; l < 2; l++) {
            int idx = tid + l * 256;
            int kr = idx >> 5;
            int c = (idx & 31) * 4;
            bReg[l] = *(const float4*)&Bsrc[(size_t)(brow + kr) * N + n0 + c];
        }
    };

    auto STS_chunk = [&](auto bufc) {
        constexpr int buf = decltype(bufc)::value;
        #pragma unroll
        for (int l = 0; l < 2; l++) {
            int m = fa_m + l * 64;
            As[buf][m][fa_s0 + 0] = f2tf(aReg[l].x);
            As[buf][m][fa_s0 + 2] = f2tf(aReg[l].y);
            As[buf][m][fa_s0 + 4] = f2tf(aReg[l].z);
            As[buf][m][fa_s0 + 6] = f2tf(aReg[l].w);
        }
        #pragma unroll
        for (int l = 0; l < 2; l++) {
            int idx = tid + l * 256;
            int kr = idx >> 5;
            int c = (idx & 31) * 4;
            *(uint4*)&Bs[buf][kr][c] =
                make_uint4(f2tf(bReg[l].x), f2tf(bReg[l].y), f2tf(bReg[l].z), f2tf(bReg[l].w));
        }
    };

    auto MMA_chunk = [&](auto bufc) {
        constexpr int buf = decltype(bufc)::value;
        #pragma unroll
        for (int kk = 0; kk < 16; kk += 8) {
            uint32_t afr[4][4], bfr[4][2];
            #pragma unroll
            for (int mt = 0; mt < 4; mt++) {
                int mb = warp_m * 64 + mt * 16;
                uint2 lo = *(const uint2*)&As[buf][mb + r][kk + 2 * cq];
                uint2 hi = *(const uint2*)&As[buf][mb + r + 8][kk + 2 * cq];
                afr[mt][0] = lo.x; afr[mt][1] = hi.x;
                afr[mt][2] = lo.y; afr[mt][3] = hi.y;
            }
            #pragma unroll
            for (int nt = 0; nt < 4; nt++) {
                int nb = warp_n * 32 + nt * 8;
                bfr[nt][0] = Bs[buf][kk + cq][nb + r];
                bfr[nt][1] = Bs[buf][kk + cq + 4][nb + r];
            }
            #pragma unroll
            for (int mt = 0; mt < 4; mt++)
                #pragma unroll
                for (int nt = 0; nt < 4; nt++)
                    mma_tf32(acc[mt][nt], afr[mt], bfr[nt]);
        }
    };

    std::integral_constant<int, 0> B0;
    std::integral_constant<int, 1> B1;

    const int NC = KT / 16;     // 8 or 16, always even
    LDG_chunk(0);
    STS_chunk(B0);
    __syncthreads();
    #pragma unroll 1
    for (int c = 0; c < NC; c += 2) {
        LDG_chunk((c + 1) * 16);
        MMA_chunk(B0);
        STS_chunk(B1);
        __syncthreads();
        if (c + 2 < NC) LDG_chunk((c + 2) * 16);
        MMA_chunk(B1);
        if (c + 2 < NC) {
            STS_chunk(B0);
            __syncthreads();
        }
    }

    float* C = (CMODE == 0) ? Cp : (CMODE == 1 ? g_xproj : g_h);
    #pragma unroll
    for (int mt = 0; mt < 4; mt++) {
        int mA = m0 + warp_m * 64 + mt * 16 + r;
        #pragma unroll
        for (int nt = 0; nt < 4; nt++) {
            int n = n0 + warp_n * 32 + nt * 8 + 2 * cq;
            if (mA < M) {
                float2 v = make_float2(acc[mt][nt][0], acc[mt][nt][1]);
                if (HAS_BIAS) { v.x += bias[n]; v.y += bias[n + 1]; }
                if (ADD_C) {
                    float2 o = *(const float2*)&C[(size_t)mA * N + n];
                    v.x += o.x; v.y += o.y;
                }
                *(float2*)&C[(size_t)mA * N + n] = v;
            }
            int mB = mA + 8;
            if (mB < M) {
                float2 v = make_float2(acc[mt][nt][2], acc[mt][nt][3]);
                if (HAS_BIAS) { v.x += bias[n]; v.y += bias[n + 1]; }
                if (ADD_C) {
                    float2 o = *(const float2*)&C[(size_t)mB * N + n];
                    v.x += o.x; v.y += o.y;
                }
                *(float2*)&C[(size_t)mB * N + n] = v;
            }
        }
    }
}

// ---------------- pull aggregation: warp per node ----------------
__global__ void k_agg1()
{
    int n = blockIdx.x * (blockDim.x >> 5) + (threadIdx.x >> 5);
    if (n >= N_NODES) return;
    int lane = threadIdx.x & 31;
    int beg = g_off[n], end = g_off[n + 1];
    float4 acc = make_float4(0.f, 0.f, 0.f, 0.f);
    for (int p = beg; p < end; p++) {
        int pk = g_pack[p];
        int src = pk & 0x1FFFF;
        int rl = pk >> 17;
        float w = g_pw[p];
        float4 v = *((const float4*)(g_xproj + ((size_t)src * RELS + rl) * DIM) + lane);
        acc.x += w * v.x; acc.y += w * v.y; acc.z += w * v.z; acc.w += w * v.w;
    }
    *((float4*)(g_h + (size_t)n * DIM) + lane) = acc;
}

__global__ void k_agg2()
{
    int n = blockIdx.x * (blockDim.x >> 5) + (threadIdx.x >> 5);
    if (n >= N_NODES) return;
    int lane = threadIdx.x & 31;
    int beg = g_off[n], end = g_off[n + 1];
    float4 acc = make_float4(0.f, 0.f, 0.f, 0.f);
    for (int p = beg; p < end; p++) {
        int src = g_pack[p] & 0x1FFFF;
        float4 v = *((const float4*)(g_h + (size_t)src * DIM) + lane);
        acc.x += v.x; acc.y += v.y; acc.z += v.z; acc.w += v.w;
    }
    *((float4*)(g_agg2 + (size_t)n * DIM) + lane) = acc;
}

// ---------------- launch ----------------
extern "C" void kernel_launch(void* const* d_in, const int* in_sizes, int n_in,
                              void* d_out, int out_size)
{
    const float* x      = (const float*)d_in[0];
    const int*   ei     = (const int*)d_in[1];    // int64 in reference -> delivered as int32
    const int*   et     = (const int*)d_in[2];
    const float* norm   = (const float*)d_in[3];
    const float* basis  = (const float*)d_in[4];
    const float* comp   = (const float*)d_in[5];
    const float* root   = (const float*)d_in[6];
    const float* bias1  = (const float*)d_in[7];
    const float* w_rel  = (const float*)d_in[8];
    const float* b_rel  = (const float*)d_in[9];
    const float* w_root = (const float*)d_in[10];
    float* out = (float*)d_out;

    const int MBLK = (N_NODES + 127) / 128;

    // one-time side-stream/event setup (host-side handles only; no device memory)
    static cudaStream_t s_side = nullptr;
    static cudaEvent_t ev_fork = nullptr, ev_join = nullptr;
    if (s_side == nullptr) {
        cudaStreamCreateWithFlags(&s_side, cudaStreamNonBlocking);
        cudaEventCreateWithFlags(&ev_fork, cudaEventDisableTiming);
        cudaEventCreateWithFlags(&ev_join, cudaEventDisableTiming);
    }

    // ---- fork: CSR build on side stream, W + big GEMM on main stream ----
    cudaEventRecord(ev_fork, 0);
    cudaStreamWaitEvent(s_side, ev_fork, 0);
    k_zero_deg<<<(N_NODES + 256) / 256, 256, 0, s_side>>>();
    k_hist<<<(N_EDGES + 255) / 256, 256, 0, s_side>>>(ei);
    k_scan<<<1, 1024, 0, s_side>>>();
    k_scatter<<<(N_EDGES + 255) / 256, 256, 0, s_side>>>(ei, et, norm);
    cudaEventRecord(ev_join, s_side);

    k_W<<<(RELS * DIM * DIM + 255) / 256, 256>>>(basis, comp);
    {   // x_proj = x @ W2   [50000,128] x [128,1024]
        dim3 grid(NR / 128, MBLK);
        k_gemm_tc<128, 0, 1, 1, false, false><<<grid, 256>>>(x, nullptr, nullptr, nullptr,
                                                             N_NODES, NR, nullptr);
    }
    // ---- join ----
    cudaStreamWaitEvent(0, ev_join, 0);

    // layer-1 aggregation -> g_h
    k_agg1<<<(N_NODES + 7) / 8, 256>>>();
    // h = agg + x @ root + bias1  (accumulate onto g_h)
    {
        dim3 grid(1, MBLK);
        k_gemm_tc<128, 0, 0, 2, true, true><<<grid, 256>>>(x, root, nullptr, nullptr,
                                                           N_NODES, DIM, bias1);
    }
    // layer-2 aggregation -> g_agg2
    k_agg2<<<(N_NODES + 7) / 8, 256>>>();
    // out = [agg2, h] @ [w_rel; w_root] + b_rel   (fused K=256)
    {
        dim3 grid(1, MBLK);
        k_gemm_tc<256, 3, 2, 0, false, true><<<grid, 256>>>(nullptr, w_rel, w_root, out,
                                                            N_NODES, DIM, b_rel);
    }
}